// round 2
// baseline (speedup 1.0000x reference)
#include <cuda_runtime.h>
#include <math.h>

// ---------------- static device scratch (no allocations allowed) ----------------
#define NK 512
#define BATCH 4096
#define NCH (BATCH * 25 * 16)      // 1,638,400 conv2 chains (window * oc)

__device__ float          g_cs[NK];        // sorted centroid values
__device__ int            g_order[NK];     // argsort order
__device__ float          g_cent[NK];      // raw centroid values
__device__ unsigned short g_add16[NK * NK];        // add_lut as u16 (512KB)
__device__ unsigned short g_P1[25 * NK * 8];       // conv1 products, oc padded to 8
__device__ unsigned short g_P2[150 * NK * 16];     // conv2 products
__device__ unsigned short g_bias1[NK * 8];
__device__ unsigned short g_bias2[NK * 16];
__device__ unsigned short g_relu[NK];
__device__ unsigned short g_sym[BATCH * 32 * 32];  // discretized input
__device__ unsigned short g_x1[BATCH * 14 * 14 * 6];
__device__ unsigned short g_x2[BATCH * 5 * 5 * 16];

// conv2 split-fold scratch
__device__ __align__(16) unsigned char g_sorted[(size_t)NCH * 160]; // sorted values (v&127), 160B/chain
__device__ unsigned int   g_off[NCH];     // packed range offsets s1|s2<<8|s3<<16
__device__ unsigned short g_acc[NCH];     // fold accumulator between passes

// ---------------- prep: stable sort of centroids ----------------
__global__ void k_sortcent(const float* __restrict__ centroid_lut) {
    __shared__ float c[NK];
    int t = threadIdx.x;
    c[t] = centroid_lut[t];
    __syncthreads();
    float ci = c[t];
    int rank = 0;
    for (int j = 0; j < NK; j++) {
        float cj = c[j];
        rank += (cj < ci) || (cj == ci && j < t);
    }
    g_cs[rank]    = ci;
    g_order[rank] = t;
    g_cent[t]     = ci;
}

// ---------------- prep: packed LUT tables ----------------
__global__ void k_prep(const int* __restrict__ conv_lut, const int* __restrict__ add_lut,
                       const int* __restrict__ c1w, const int* __restrict__ c2w,
                       const int* __restrict__ b1, const int* __restrict__ b2,
                       const int* __restrict__ relu) {
    int i = blockIdx.x * blockDim.x + threadIdx.x;
    if (i < NK * NK) { g_add16[i] = (unsigned short)add_lut[i]; return; }
    i -= NK * NK;
    if (i < 25 * NK * 8) {
        int oc = i & 7; int s = (i >> 3) & (NK - 1); int j = i >> 12;
        int occ = oc < 6 ? oc : 5;
        g_P1[i] = (unsigned short)conv_lut[s * NK + c1w[j * 6 + occ]];
        return;
    }
    i -= 25 * NK * 8;
    if (i < 150 * NK * 16) {
        int oc = i & 15; int s = (i >> 4) & (NK - 1); int j = i >> 13;
        g_P2[i] = (unsigned short)conv_lut[s * NK + c2w[j * 16 + oc]];
        return;
    }
    i -= 150 * NK * 16;
    if (i < NK * 8) {
        int oc = i & 7; int s = i >> 3; int occ = oc < 6 ? oc : 5;
        g_bias1[i] = (unsigned short)b1[s * 6 + occ];
        return;
    }
    i -= NK * 8;
    if (i < NK * 16) { g_bias2[i] = (unsigned short)b2[i]; return; }
    i -= NK * 16;
    if (i < NK) g_relu[i] = (unsigned short)relu[i];
}

// ---------------- discretize ----------------
__global__ void k_disc(const float* __restrict__ x) {
    __shared__ float cs[NK];
    __shared__ int   ord[NK];
    int t = threadIdx.x;
    for (int i = t; i < NK; i += blockDim.x) { cs[i] = g_cs[i]; ord[i] = g_order[i]; }
    __syncthreads();
    int idx = blockIdx.x * blockDim.x + t;
    float v = x[idx];
    int lo = 0, hi = NK;
    #pragma unroll
    for (int it = 0; it < 9; it++) {
        int m = (lo + hi) >> 1;
        if (cs[m] < v) lo = m + 1; else hi = m;
    }
    int l = lo - 1; if (l < 0) l = 0;
    int h = lo;     if (h > NK - 1) h = NK - 1;
    float dl = fabsf(v - cs[l]);
    float dh = fabsf(v - cs[h]);
    g_sym[idx] = (unsigned short)ord[(dl <= dh) ? l : h];
}

// ---------------- conv1: register bitonic sort + LUT fold (unchanged) ----------------
__global__ void __launch_bounds__(128) k_conv1() {
    int id  = blockIdx.x * 128 + threadIdx.x;
    int oc  = id % 6;
    int win = id / 6;
    int b   = win / 196;
    int r   = win % 196;
    int oy  = r / 14, ox = r % 14;

    const unsigned short* base = g_sym + (b * 32 + oy * 2) * 32 + ox * 2;
    unsigned v[32];
    #pragma unroll
    for (int ky = 0; ky < 5; ky++)
        #pragma unroll
        for (int kx = 0; kx < 5; kx++) {
            unsigned s = base[ky * 32 + kx];
            v[ky * 5 + kx] = g_P1[((ky * 5 + kx) * NK + s) * 8 + oc];
        }
    #pragma unroll
    for (int i = 25; i < 32; i++) v[i] = 0xFFFFu;

    #pragma unroll
    for (int k2 = 2; k2 <= 32; k2 <<= 1) {
        #pragma unroll
        for (int j = k2 >> 1; j > 0; j >>= 1) {
            #pragma unroll
            for (int i = 0; i < 32; i++) {
                int l = i ^ j;
                if (l > i) {
                    bool up = ((i & k2) == 0);
                    unsigned a = v[i], c = v[l];
                    unsigned mn = a < c ? a : c;
                    unsigned mx = a < c ? c : a;
                    v[i] = up ? mn : mx;
                    v[l] = up ? mx : mn;
                }
            }
        }
    }

    unsigned acc = v[0];
    #pragma unroll
    for (int i = 1; i < 25; i++) acc = g_add16[v[i] * NK + acc];

    unsigned t2 = g_bias1[acc * 8 + oc];
    g_x1[((b * 14 + oy) * 14 + ox) * 6 + oc] = g_relu[t2];
}

// ---------------- conv2 Phase A: counting sort -> sorted u8 stream + offsets ----------------
// block = 64 threads = 4 windows x 16 oc.
__global__ void __launch_bounds__(64) k_sortA() {
    __shared__ unsigned char  hist8[NK * 64];                 // 32KB
    __shared__ unsigned short syms[4 * 150];
    __shared__ __align__(4) unsigned char stage[64 * 164];    // 164B row stride (bank-friendly)
    unsigned* hist32  = (unsigned*)hist8;
    unsigned* stage32 = (unsigned*)stage;
    int tid = threadIdx.x;

    for (int i = tid; i < NK * 16; i += 64) hist32[i] = 0;

    int wbase = blockIdx.x * 4;
    for (int i = tid; i < 600; i += 64) {
        int win = i / 150, j = i % 150;
        int wg = wbase + win;
        int b = wg / 25, p = wg % 25;
        int oy = p / 5, ox = p % 5;
        int kk = j / 6, c = j % 6;
        int ky = kk / 5, kx = kk % 5;
        syms[win * 150 + j] =
            g_x1[((b * 14 + oy * 2 + ky) * 14 + (ox * 2 + kx)) * 6 + c];
    }
    __syncthreads();

    int win = tid >> 4, oc = tid & 15;
    const unsigned short* sy = syms + win * 150;
    unsigned tb = (unsigned)(tid << 2);
    unsigned m0 = 0, m1 = 0, m2 = 0, m3 = 0;     // 128-bit group occupancy mask
    for (int j = 0; j < 150; j++) {
        unsigned s = sy[j];
        unsigned v = g_P2[(j * NK + s) * 16 + oc];  // lanes 0-15 share one 32B sector
        hist8[(v >> 2) * 256 + tb + (v & 3)]++;     // own byte column: no races
        unsigned g = v >> 2;
        unsigned bitm = 1u << (g & 31);
        if (g < 64) { if (g < 32) m0 |= bitm; else m1 |= bitm; }
        else        { if (g < 96) m2 |= bitm; else m3 |= bitm; }
    }

    // extraction: ascending order, masked groups only (no dependent-LDS scan)
    int pos = 0;
    unsigned srow = tid * 164;
    unsigned s1 = 0, s2 = 0, s3 = 0;
    #pragma unroll
    for (int w = 0; w < 4; w++) {
        unsigned mw = (w == 0) ? m0 : (w == 1) ? m1 : (w == 2) ? m2 : m3;
        while (mw) {
            int g2 = __ffs(mw) - 1; mw &= mw - 1;
            int g = w * 32 + g2;
            unsigned word = hist32[g * 64 + tid];
            #pragma unroll
            for (int by = 0; by < 4; by++) {
                int c = (word >> (8 * by)) & 255;
                unsigned char vloc = (unsigned char)((g2 << 2) | by);   // v & 127
                for (int q = 0; q < c; q++) stage[srow + (pos++)] = vloc;
            }
        }
        if (w == 0) s1 = pos; else if (w == 1) s2 = pos; else if (w == 2) s3 = pos;
    }
    g_off[blockIdx.x * 64 + tid] = s1 | (s2 << 8) | (s3 << 16);

    __syncthreads();
    // coalesced flush: 64 rows x 160B -> global (u32 granularity)
    unsigned gbase = blockIdx.x * 2560;            // in u32 units
    unsigned* gs32 = (unsigned*)g_sorted;
    for (int i = tid; i < 2560; i += 64) {
        int t = i / 40, j = i % 40;                // 40 u32 per 160B row
        gs32[gbase + i] = stage32[t * 41 + j];     // stage stride 41 u32
    }
}

// ---------------- conv2 fold pass r: add_lut rows [128r,128r+128) in SMEM ----------------
__global__ void __launch_bounds__(1024, 1) k_fold(int r) {
    extern __shared__ unsigned short tbl[];        // 128 rows x 512 u16 = 128KB
    int tid = threadIdx.x;
    const uint4* src = (const uint4*)(g_add16 + r * 65536);
    uint4* dst = (uint4*)tbl;
    for (int i = tid; i < 8192; i += 1024) dst[i] = src[i];
    __syncthreads();

    for (int chain = blockIdx.x * 1024 + tid; chain < NCH; chain += gridDim.x * 1024) {
        unsigned off = g_off[chain];
        int start = (r == 0) ? 0   : (int)((off >> (8 * (r - 1))) & 255);
        int end   = (r == 3) ? 150 : (int)((off >> (8 * r)) & 255);
        unsigned acc = (r == 0) ? 0xFFFFu : (unsigned)g_acc[chain];
        const unsigned long long* row =
            (const unsigned long long*)(g_sorted + (size_t)chain * 160);
        int i = start;
        if (i < end) {
            unsigned long long buf = row[i >> 3];
            if (acc == 0xFFFFu) {                  // first value overall initializes acc
                acc = (unsigned)(r << 7) + ((unsigned)(buf >> ((i & 7) * 8)) & 255u);
                ++i;
                if ((i & 7) == 0 && i < end) buf = row[i >> 3];
            }
            while (i < end) {
                unsigned vloc = (unsigned)(buf >> ((i & 7) * 8)) & 255u;
                acc = tbl[(vloc << 9) + acc];      // SMEM gather: ~bank conflicts only
                ++i;
                if ((i & 7) == 0 && i < end) buf = row[i >> 3];
            }
        }
        if (r < 3) {
            g_acc[chain] = (unsigned short)acc;
        } else {
            unsigned t2 = g_bias2[acc * 16 + (chain & 15)];
            g_x2[chain] = g_relu[t2];
        }
    }
}

// ---------------- FC stack + softmax ----------------
__global__ void __launch_bounds__(128) k_fc(
    const float* __restrict__ w1, const float* __restrict__ fb1,
    const float* __restrict__ w2, const float* __restrict__ fb2,
    const float* __restrict__ w3, const float* __restrict__ fb3,
    float* __restrict__ out) {
    __shared__ __align__(16) float feat[400];
    __shared__ __align__(16) float h1[120];
    __shared__ __align__(16) float h2[84];
    __shared__ float lg[10];
    int b = blockIdx.x, t = threadIdx.x;

    for (int i = t; i < 400; i += 128) {
        int c = i / 25, r = i % 25;
        unsigned s = g_x2[(b * 25 + r) * 16 + c];
        feat[i] = g_cent[s];
    }
    __syncthreads();

    if (t < 120) {
        float acc = fb1[t];
        const float4* wr = (const float4*)(w1 + t * 400);
        const float4* fr = (const float4*)feat;
        #pragma unroll 5
        for (int k = 0; k < 100; k++) {
            float4 a = wr[k], f = fr[k];
            acc += a.x * f.x + a.y * f.y + a.z * f.z + a.w * f.w;
        }
        h1[t] = 1.f / (1.f + expf(-acc));
    }
    __syncthreads();
    if (t < 84) {
        float acc = fb2[t];
        const float4* wr = (const float4*)(w2 + t * 120);
        const float4* fr = (const float4*)h1;
        #pragma unroll 5
        for (int k = 0; k < 30; k++) {
            float4 a = wr[k], f = fr[k];
            acc += a.x * f.x + a.y * f.y + a.z * f.z + a.w * f.w;
        }
        h2[t] = 1.f / (1.f + expf(-acc));
    }
    __syncthreads();
    if (t < 10) {
        float acc = fb3[t];
        const float4* wr = (const float4*)(w3 + t * 84);
        const float4* fr = (const float4*)h2;
        #pragma unroll
        for (int k = 0; k < 21; k++) {
            float4 a = wr[k], f = fr[k];
            acc += a.x * f.x + a.y * f.y + a.z * f.z + a.w * f.w;
        }
        lg[t] = acc;
    }
    __syncthreads();
    if (t < 10) {
        float m = lg[0];
        #pragma unroll
        for (int i = 1; i < 10; i++) m = fmaxf(m, lg[i]);
        float s = 0.f;
        #pragma unroll
        for (int i = 0; i < 10; i++) s += expf(lg[i] - m);
        out[b * 10 + t] = expf(lg[t] - m) / s;
    }
}

// ---------------- launch ----------------
extern "C" void kernel_launch(void* const* d_in, const int* in_sizes, int n_in,
                              void* d_out, int out_size) {
    const float* x        = (const float*)d_in[0];
    const float* cent     = (const float*)d_in[1];
    const int*   c1w      = (const int*)d_in[2];
    const int*   c2w      = (const int*)d_in[3];
    const int*   conv_lut = (const int*)d_in[4];
    const int*   add_lut  = (const int*)d_in[5];
    const int*   b1l      = (const int*)d_in[6];
    const int*   b2l      = (const int*)d_in[7];
    const int*   relu     = (const int*)d_in[8];
    const float* w1  = (const float*)d_in[9];
    const float* fb1 = (const float*)d_in[10];
    const float* w2  = (const float*)d_in[11];
    const float* fb2 = (const float*)d_in[12];
    const float* w3  = (const float*)d_in[13];
    const float* fb3 = (const float*)d_in[14];
    float* out = (float*)d_out;

    cudaFuncSetAttribute(k_fold, cudaFuncAttributeMaxDynamicSharedMemorySize, 131072);

    k_sortcent<<<1, 512>>>(cent);

    const int prepN = NK * NK + 25 * NK * 8 + 150 * NK * 16 + NK * 8 + NK * 16 + NK;
    k_prep<<<(prepN + 255) / 256, 256>>>(conv_lut, add_lut, c1w, c2w, b1l, b2l, relu);

    k_disc<<<(BATCH * 1024) / 256, 256>>>(x);
    k_conv1<<<(BATCH * 196 * 6) / 128, 128>>>();
    k_sortA<<<(BATCH * 25) / 4, 64>>>();
    for (int r = 0; r < 4; r++) k_fold<<<148, 1024, 131072>>>(r);
    k_fc<<<BATCH, 128>>>(w1, fb1, w2, fb2, w3, fb3, out);
}

// round 3
// speedup vs baseline: 1.9609x; 1.9609x over previous
#include <cuda_runtime.h>
#include <math.h>

// ---------------- static device scratch (no allocations allowed) ----------------
#define NK 512
#define BATCH 4096

__device__ float          g_cs[NK];        // sorted centroid values
__device__ int            g_order[NK];     // argsort order
__device__ float          g_cent[NK];      // raw centroid values
__device__ unsigned short g_add16[NK * NK];        // add_lut as u16 (512KB)
__device__ unsigned short g_P1[25 * NK * 8];       // conv1 products, oc padded to 8
__device__ unsigned short g_P2[150 * NK * 16];     // conv2 products
__device__ unsigned short g_bias1[NK * 8];
__device__ unsigned short g_bias2[NK * 16];
__device__ unsigned short g_relu[NK];
__device__ unsigned short g_sym[BATCH * 32 * 32];  // discretized input
__device__ unsigned short g_x1[BATCH * 14 * 14 * 6];
__device__ unsigned short g_x2[BATCH * 5 * 5 * 16];

// ---------------- prep: stable sort of centroids ----------------
__global__ void k_sortcent(const float* __restrict__ centroid_lut) {
    __shared__ float c[NK];
    int t = threadIdx.x;
    c[t] = centroid_lut[t];
    __syncthreads();
    float ci = c[t];
    int rank = 0;
    for (int j = 0; j < NK; j++) {
        float cj = c[j];
        rank += (cj < ci) || (cj == ci && j < t);
    }
    g_cs[rank]    = ci;
    g_order[rank] = t;
    g_cent[t]     = ci;
}

// ---------------- prep: packed LUT tables ----------------
__global__ void k_prep(const int* __restrict__ conv_lut, const int* __restrict__ add_lut,
                       const int* __restrict__ c1w, const int* __restrict__ c2w,
                       const int* __restrict__ b1, const int* __restrict__ b2,
                       const int* __restrict__ relu) {
    int i = blockIdx.x * blockDim.x + threadIdx.x;
    if (i < NK * NK) { g_add16[i] = (unsigned short)add_lut[i]; return; }
    i -= NK * NK;
    if (i < 25 * NK * 8) {
        int oc = i & 7; int s = (i >> 3) & (NK - 1); int j = i >> 12;
        int occ = oc < 6 ? oc : 5;
        g_P1[i] = (unsigned short)conv_lut[s * NK + c1w[j * 6 + occ]];
        return;
    }
    i -= 25 * NK * 8;
    if (i < 150 * NK * 16) {
        int oc = i & 15; int s = (i >> 4) & (NK - 1); int j = i >> 13;
        g_P2[i] = (unsigned short)conv_lut[s * NK + c2w[j * 16 + oc]];
        return;
    }
    i -= 150 * NK * 16;
    if (i < NK * 8) {
        int oc = i & 7; int s = i >> 3; int occ = oc < 6 ? oc : 5;
        g_bias1[i] = (unsigned short)b1[s * 6 + occ];
        return;
    }
    i -= NK * 8;
    if (i < NK * 16) { g_bias2[i] = (unsigned short)b2[i]; return; }
    i -= NK * 16;
    if (i < NK) g_relu[i] = (unsigned short)relu[i];
}

// ---------------- discretize ----------------
__global__ void k_disc(const float* __restrict__ x) {
    __shared__ float cs[NK];
    __shared__ int   ord[NK];
    int t = threadIdx.x;
    for (int i = t; i < NK; i += blockDim.x) { cs[i] = g_cs[i]; ord[i] = g_order[i]; }
    __syncthreads();
    int idx = blockIdx.x * blockDim.x + t;
    float v = x[idx];
    int lo = 0, hi = NK;
    #pragma unroll
    for (int it = 0; it < 9; it++) {
        int m = (lo + hi) >> 1;
        if (cs[m] < v) lo = m + 1; else hi = m;
    }
    int l = lo - 1; if (l < 0) l = 0;
    int h = lo;     if (h > NK - 1) h = NK - 1;
    float dl = fabsf(v - cs[l]);
    float dh = fabsf(v - cs[h]);
    g_sym[idx] = (unsigned short)ord[(dl <= dh) ? l : h];
}

// ---------------- conv1: register bitonic sort + LUT fold ----------------
__global__ void __launch_bounds__(128) k_conv1() {
    int id  = blockIdx.x * 128 + threadIdx.x;
    int oc  = id % 6;
    int win = id / 6;
    int b   = win / 196;
    int r   = win % 196;
    int oy  = r / 14, ox = r % 14;

    const unsigned short* base = g_sym + (b * 32 + oy * 2) * 32 + ox * 2;
    unsigned v[32];
    #pragma unroll
    for (int ky = 0; ky < 5; ky++)
        #pragma unroll
        for (int kx = 0; kx < 5; kx++) {
            unsigned s = base[ky * 32 + kx];
            v[ky * 5 + kx] = g_P1[((ky * 5 + kx) * NK + s) * 8 + oc];
        }
    #pragma unroll
    for (int i = 25; i < 32; i++) v[i] = 0xFFFFu;

    #pragma unroll
    for (int k2 = 2; k2 <= 32; k2 <<= 1) {
        #pragma unroll
        for (int j = k2 >> 1; j > 0; j >>= 1) {
            #pragma unroll
            for (int i = 0; i < 32; i++) {
                int l = i ^ j;
                if (l > i) {
                    bool up = ((i & k2) == 0);
                    unsigned a = v[i], c = v[l];
                    unsigned mn = a < c ? a : c;
                    unsigned mx = a < c ? c : a;
                    v[i] = up ? mn : mx;
                    v[l] = up ? mx : mn;
                }
            }
        }
    }

    unsigned acc = v[0];
    #pragma unroll
    for (int i = 1; i < 25; i++) acc = g_add16[v[i] * NK + acc];

    unsigned t2 = g_bias1[acc * 8 + oc];
    g_x1[((b * 14 + oy) * 14 + ox) * 6 + oc] = g_relu[t2];
}

// ---------------- conv2: nibble-histogram counting sort + mask cursor fold ----------
// block = 128 threads = 8 windows x 16 oc.
// hist: 4-bit counts, word per (group g = v>>3, tid); nibble slot = v&7.
//   bank(word) = (g*128 + tid) % 32 = tid % 32  -> conflict-free RMW and reads.
// 64-bit register mask of nonzero groups -> cursor jumps straight to next group.
// Fold: exactly 150 lockstep steps per lane (lookup fully converged).
__global__ void __launch_bounds__(128) k_conv2() {
    __shared__ unsigned int   hist[64 * 128];      // 32KB nibble counts
    __shared__ unsigned short syms[8 * 150];       // 2.4KB
    int tid = threadIdx.x;

    #pragma unroll
    for (int i = 0; i < 64; i++) hist[i * 128 + tid] = 0;

    int wbase = blockIdx.x * 8;
    for (int i = tid; i < 1200; i += 128) {
        int win = i / 150, j = i % 150;
        int wg = wbase + win;
        int b = wg / 25, p = wg % 25;
        int oy = p / 5, ox = p % 5;
        int kk = j / 6, c = j % 6;
        int ky = kk / 5, kx = kk % 5;
        syms[win * 150 + j] =
            g_x1[((b * 14 + oy * 2 + ky) * 14 + (ox * 2 + kx)) * 6 + c];
    }
    __syncthreads();

    int win = tid >> 4, oc = tid & 15;
    const unsigned short* sy = syms + win * 150;
    unsigned long long mask = 0ull;
    for (int j = 0; j < 150; j++) {
        unsigned s = sy[j];
        unsigned v = g_P2[(j * NK + s) * 16 + oc];   // lanes 0-15 share one 32B sector
        unsigned g = v >> 3;
        hist[g * 128 + tid] += 1u << (4 * (v & 7));  // own word: no races
        mask |= 1ull << g;
    }

    // cursor fold: 150 lockstep extract+lookup steps
    unsigned acc = 0;
    unsigned w = 0;
    int g = 0;
    for (int step = 0; step < 150; ++step) {
        while (w == 0) {                              // pull next nonzero group
            g = __ffsll((long long)mask) - 1;
            mask &= mask - 1;
            w = hist[g * 128 + tid];
        }
        int bit = __ffs((int)w) - 1;
        int by  = bit >> 2;                           // nibble slot
        unsigned v = (unsigned)(g * 8 + by);
        w -= 1u << (by << 2);
        acc = (step == 0) ? v : (unsigned)g_add16[v * NK + acc];
    }

    unsigned t2 = g_bias2[acc * 16 + oc];
    int wg = wbase + win;
    g_x2[wg * 16 + oc] = g_relu[t2];
}

// ---------------- FC stack + softmax ----------------
__global__ void __launch_bounds__(128) k_fc(
    const float* __restrict__ w1, const float* __restrict__ fb1,
    const float* __restrict__ w2, const float* __restrict__ fb2,
    const float* __restrict__ w3, const float* __restrict__ fb3,
    float* __restrict__ out) {
    __shared__ __align__(16) float feat[400];
    __shared__ __align__(16) float h1[120];
    __shared__ __align__(16) float h2[84];
    __shared__ float lg[10];
    int b = blockIdx.x, t = threadIdx.x;

    for (int i = t; i < 400; i += 128) {
        int c = i / 25, r = i % 25;
        unsigned s = g_x2[(b * 25 + r) * 16 + c];
        feat[i] = g_cent[s];
    }
    __syncthreads();

    if (t < 120) {
        float acc = fb1[t];
        const float4* wr = (const float4*)(w1 + t * 400);
        const float4* fr = (const float4*)feat;
        #pragma unroll 5
        for (int k = 0; k < 100; k++) {
            float4 a = wr[k], f = fr[k];
            acc += a.x * f.x + a.y * f.y + a.z * f.z + a.w * f.w;
        }
        h1[t] = 1.f / (1.f + expf(-acc));
    }
    __syncthreads();
    if (t < 84) {
        float acc = fb2[t];
        const float4* wr = (const float4*)(w2 + t * 120);
        const float4* fr = (const float4*)h1;
        #pragma unroll 5
        for (int k = 0; k < 30; k++) {
            float4 a = wr[k], f = fr[k];
            acc += a.x * f.x + a.y * f.y + a.z * f.z + a.w * f.w;
        }
        h2[t] = 1.f / (1.f + expf(-acc));
    }
    __syncthreads();
    if (t < 10) {
        float acc = fb3[t];
        const float4* wr = (const float4*)(w3 + t * 84);
        const float4* fr = (const float4*)h2;
        #pragma unroll
        for (int k = 0; k < 21; k++) {
            float4 a = wr[k], f = fr[k];
            acc += a.x * f.x + a.y * f.y + a.z * f.z + a.w * f.w;
        }
        lg[t] = acc;
    }
    __syncthreads();
    if (t < 10) {
        float m = lg[0];
        #pragma unroll
        for (int i = 1; i < 10; i++) m = fmaxf(m, lg[i]);
        float s = 0.f;
        #pragma unroll
        for (int i = 0; i < 10; i++) s += expf(lg[i] - m);
        out[b * 10 + t] = expf(lg[t] - m) / s;
    }
}

// ---------------- launch ----------------
extern "C" void kernel_launch(void* const* d_in, const int* in_sizes, int n_in,
                              void* d_out, int out_size) {
    const float* x        = (const float*)d_in[0];
    const float* cent     = (const float*)d_in[1];
    const int*   c1w      = (const int*)d_in[2];
    const int*   c2w      = (const int*)d_in[3];
    const int*   conv_lut = (const int*)d_in[4];
    const int*   add_lut  = (const int*)d_in[5];
    const int*   b1l      = (const int*)d_in[6];
    const int*   b2l      = (const int*)d_in[7];
    const int*   relu     = (const int*)d_in[8];
    const float* w1  = (const float*)d_in[9];
    const float* fb1 = (const float*)d_in[10];
    const float* w2  = (const float*)d_in[11];
    const float* fb2 = (const float*)d_in[12];
    const float* w3  = (const float*)d_in[13];
    const float* fb3 = (const float*)d_in[14];
    float* out = (float*)d_out;

    k_sortcent<<<1, 512>>>(cent);

    const int prepN = NK * NK + 25 * NK * 8 + 150 * NK * 16 + NK * 8 + NK * 16 + NK;
    k_prep<<<(prepN + 255) / 256, 256>>>(conv_lut, add_lut, c1w, c2w, b1l, b2l, relu);

    k_disc<<<(BATCH * 1024) / 256, 256>>>(x);
    k_conv1<<<(BATCH * 196 * 6) / 128, 128>>>();
    k_conv2<<<(BATCH * 25) / 8, 128>>>();          // 12800 blocks, 8 windows each
    k_fc<<<BATCH, 128>>>(w1, fb1, w2, fb2, w3, fb3, out);
}